// round 10
// baseline (speedup 1.0000x reference)
#include <cuda_runtime.h>
#include <cuda_bf16.h>
#include <cstdint>

#define B_  8
#define T_  1024
#define DM_ 1024
#define H_  16
#define D_  64
#define BH_ (B_ * H_)
#define NEGV (-1.0e9f)

// Scratch (allocation-free rule: __device__ globals)
__device__ float g_qh[BH_ * T_ * D_];
__device__ float g_kh[BH_ * T_ * D_];
__device__ float g_vh[BH_ * T_ * D_];
__device__ float g_ctx[BH_ * T_ * D_];
__device__ float g_linv[BH_ * T_];

// ---------------------------------------------------------------------------
// mma.sync bf16 (baseline PTX -> legacy HMMA on sm_103)
// ---------------------------------------------------------------------------
__device__ __forceinline__ void mma_bf16(float c[4],
                                         uint32_t a0, uint32_t a1,
                                         uint32_t a2, uint32_t a3,
                                         uint32_t b0, uint32_t b1) {
    asm volatile(
        "mma.sync.aligned.m16n8k16.row.col.f32.bf16.bf16.f32 "
        "{%0,%1,%2,%3}, {%4,%5,%6,%7}, {%8,%9}, {%0,%1,%2,%3};"
        : "+f"(c[0]), "+f"(c[1]), "+f"(c[2]), "+f"(c[3])
        : "r"(a0), "r"(a1), "r"(a2), "r"(a3), "r"(b0), "r"(b1));
}

__device__ __forceinline__ uint32_t pack_bf16x2(float x, float y) {
    __nv_bfloat162 h = __floats2bfloat162_rn(x, y);
    return *reinterpret_cast<uint32_t*>(&h);
}

// ---------------------------------------------------------------------------
// Kernel 1: projection GEMM via mma.sync bf16x3 (hi/lo split).
// C[m][n] = sum_k X[m][k]*W[n][k] + bias[n];  M=8192, N=1024, K=1024.
// CTA 128x128, 8 warps (2x4), warp tile 64x32, K-chunk 32.
// ---------------------------------------------------------------------------
#define KC 32
#define PITCH 20
#define TILE_U32 (128 * PITCH)
#define PROJ_SMEM (4 * TILE_U32 * 4)

__global__ __launch_bounds__(256) void proj_mma_kernel(
    const float* __restrict__ X, const float* __restrict__ W,
    const float* __restrict__ bias, float* __restrict__ out) {
    extern __shared__ uint32_t sm[];
    uint32_t* Ahi = sm;
    uint32_t* Alo = sm + TILE_U32;
    uint32_t* Bhi = sm + 2 * TILE_U32;
    uint32_t* Blo = sm + 3 * TILE_U32;

    const int tid = threadIdx.x;
    const int lane = tid & 31;
    const int warp = tid >> 5;
    const int wm = (warp >> 2) * 64;
    const int wn = (warp & 3) * 32;

    const int m0 = blockIdx.y * 128;
    const int n0 = blockIdx.x * 128;

    float c[4][4][4];
#pragma unroll
    for (int mi = 0; mi < 4; mi++)
#pragma unroll
        for (int nj = 0; nj < 4; nj++)
#pragma unroll
            for (int r = 0; r < 4; r++) c[mi][nj][r] = 0.0f;

    const int fr[4] = {(tid) >> 3, (tid + 256) >> 3, (tid + 512) >> 3, (tid + 768) >> 3};
    const int fc = (tid & 7) * 4;
    const int fc2 = (tid & 7) * 2;

    float4 ax[4], bx[4];
#pragma unroll
    for (int q = 0; q < 4; q++) {
        ax[q] = *reinterpret_cast<const float4*>(&X[(m0 + fr[q]) * DM_ + fc]);
        bx[q] = *reinterpret_cast<const float4*>(&W[(n0 + fr[q]) * DM_ + fc]);
    }

    for (int i = 0; i < DM_ / KC; i++) {
#pragma unroll
        for (int q = 0; q < 4; q++) {
            float4 v = ax[q];
            float hx = __bfloat162float(__float2bfloat16_rn(v.x));
            float hy = __bfloat162float(__float2bfloat16_rn(v.y));
            float hz = __bfloat162float(__float2bfloat16_rn(v.z));
            float hw = __bfloat162float(__float2bfloat16_rn(v.w));
            int base = fr[q] * PITCH + fc2;
            Ahi[base + 0] = pack_bf16x2(hx, hy);
            Ahi[base + 1] = pack_bf16x2(hz, hw);
            Alo[base + 0] = pack_bf16x2(v.x - hx, v.y - hy);
            Alo[base + 1] = pack_bf16x2(v.z - hz, v.w - hw);

            v = bx[q];
            hx = __bfloat162float(__float2bfloat16_rn(v.x));
            hy = __bfloat162float(__float2bfloat16_rn(v.y));
            hz = __bfloat162float(__float2bfloat16_rn(v.z));
            hw = __bfloat162float(__float2bfloat16_rn(v.w));
            Bhi[base + 0] = pack_bf16x2(hx, hy);
            Bhi[base + 1] = pack_bf16x2(hz, hw);
            Blo[base + 0] = pack_bf16x2(v.x - hx, v.y - hy);
            Blo[base + 1] = pack_bf16x2(v.z - hz, v.w - hw);
        }
        __syncthreads();

        if (i + 1 < DM_ / KC) {
            const int k0 = (i + 1) * KC;
#pragma unroll
            for (int q = 0; q < 4; q++) {
                ax[q] = *reinterpret_cast<const float4*>(&X[(m0 + fr[q]) * DM_ + k0 + fc]);
                bx[q] = *reinterpret_cast<const float4*>(&W[(n0 + fr[q]) * DM_ + k0 + fc]);
            }
        }

#pragma unroll
        for (int kb = 0; kb < 2; kb++) {
            const int cc = kb * 8 + (lane & 3);
            uint32_t ah[4][4], al[4][4], bh[4][2], bl[4][2];
#pragma unroll
            for (int mi = 0; mi < 4; mi++) {
                int r0 = wm + mi * 16 + (lane >> 2);
                ah[mi][0] = Ahi[r0 * PITCH + cc];
                ah[mi][1] = Ahi[(r0 + 8) * PITCH + cc];
                ah[mi][2] = Ahi[r0 * PITCH + cc + 4];
                ah[mi][3] = Ahi[(r0 + 8) * PITCH + cc + 4];
                al[mi][0] = Alo[r0 * PITCH + cc];
                al[mi][1] = Alo[(r0 + 8) * PITCH + cc];
                al[mi][2] = Alo[r0 * PITCH + cc + 4];
                al[mi][3] = Alo[(r0 + 8) * PITCH + cc + 4];
            }
#pragma unroll
            for (int nj = 0; nj < 4; nj++) {
                int nr = wn + nj * 8 + (lane >> 2);
                bh[nj][0] = Bhi[nr * PITCH + cc];
                bh[nj][1] = Bhi[nr * PITCH + cc + 4];
                bl[nj][0] = Blo[nr * PITCH + cc];
                bl[nj][1] = Blo[nr * PITCH + cc + 4];
            }
#pragma unroll
            for (int mi = 0; mi < 4; mi++)
#pragma unroll
                for (int nj = 0; nj < 4; nj++) {
                    mma_bf16(c[mi][nj], ah[mi][0], ah[mi][1], ah[mi][2], ah[mi][3],
                             bh[nj][0], bh[nj][1]);
                    mma_bf16(c[mi][nj], ah[mi][0], ah[mi][1], ah[mi][2], ah[mi][3],
                             bl[nj][0], bl[nj][1]);
                    mma_bf16(c[mi][nj], al[mi][0], al[mi][1], al[mi][2], al[mi][3],
                             bh[nj][0], bh[nj][1]);
                }
        }
        __syncthreads();
    }

#pragma unroll
    for (int mi = 0; mi < 4; mi++) {
        int r0 = m0 + wm + mi * 16 + (lane >> 2);
#pragma unroll
        for (int nj = 0; nj < 4; nj++) {
            int n = n0 + wn + nj * 8 + (lane & 3) * 2;
            int h = n >> 6, dd = n & 63;
            float b0 = bias[n], b1 = bias[n + 1];
#pragma unroll
            for (int half = 0; half < 2; half++) {
                int r = r0 + half * 8;
                int bb = r >> 10, t = r & 1023;
                float2 o;
                o.x = c[mi][nj][half * 2 + 0] + b0;
                o.y = c[mi][nj][half * 2 + 1] + b1;
                *reinterpret_cast<float2*>(
                    &out[(((size_t)bb * H_ + h) * T_ + t) * D_ + dd]) = o;
            }
        }
    }
}

// ---------------------------------------------------------------------------
// Kernel 2: single-pass attention, R1-proven 64x64 tiling.
// Per 64-col k-tile: s = (Q/8)K^T, mask, e = exp(s) (no max subtraction:
// scores are O(1)), write e unnormalized to attn_out, lp += e,
// ctx += e @ V via Pt staging (pitch 68, q<64: valid).
// ---------------------------------------------------------------------------
#define ATTN_SMEM ((4352 + 4352 + 4096 + 64) * 4)

__global__ __launch_bounds__(256) void attn_kernel(
    const int* __restrict__ mask, float* __restrict__ attn_out) {
    extern __shared__ float sh[];
    float* Qs = sh;             // [64 d][68 q]
    float* Ks = sh + 4352;      // [64 d][68 k]; reused as Pt[64 kc][68 q]
    float* Vs = sh + 8704;      // [64 k][64 d]
    float* sl = sh + 12800;     // [64]

    const int bh = blockIdx.y;
    const int q0 = blockIdx.x * 64;
    const int tid = threadIdx.x;
    const int tx = tid & 15, ty = tid >> 4;

    // Load Q tile (64 x 64) transposed + prescaled by 1/sqrt(D)
#pragma unroll
    for (int it = 0; it < 4; it++) {
        int f = tid + it * 256;
        int r = f >> 4;
        int d4 = (f & 15) << 2;
        float4 v = *reinterpret_cast<const float4*>(&g_qh[(bh * T_ + q0 + r) * D_ + d4]);
        Qs[(d4 + 0) * 68 + r] = v.x * 0.125f;
        Qs[(d4 + 1) * 68 + r] = v.y * 0.125f;
        Qs[(d4 + 2) * 68 + r] = v.z * 0.125f;
        Qs[(d4 + 3) * 68 + r] = v.w * 0.125f;
    }

    float c[4][4];
    float lp[4];
#pragma unroll
    for (int i = 0; i < 4; i++) {
        lp[i] = 0.0f;
#pragma unroll
        for (int j = 0; j < 4; j++) c[i][j] = 0.0f;
    }

    for (int kt = 0; kt < T_; kt += 64) {
        __syncthreads();  // prior Pt/Vs reads done (also covers Qs fill)
#pragma unroll
        for (int it = 0; it < 4; it++) {
            int f = tid + it * 256;
            int r = f >> 4;
            int d4 = (f & 15) << 2;
            float4 kv = *reinterpret_cast<const float4*>(&g_kh[(bh * T_ + kt + r) * D_ + d4]);
            Ks[(d4 + 0) * 68 + r] = kv.x;
            Ks[(d4 + 1) * 68 + r] = kv.y;
            Ks[(d4 + 2) * 68 + r] = kv.z;
            Ks[(d4 + 3) * 68 + r] = kv.w;
            float4 vv = *reinterpret_cast<const float4*>(&g_vh[(bh * T_ + kt + r) * D_ + d4]);
            *reinterpret_cast<float4*>(&Vs[r * 64 + d4]) = vv;
        }
        __syncthreads();

        // scores: rows q0+ty*4+i, cols kt+tx*4+j
        float s[4][4];
#pragma unroll
        for (int i = 0; i < 4; i++)
#pragma unroll
            for (int j = 0; j < 4; j++) s[i][j] = 0.0f;
#pragma unroll
        for (int kk = 0; kk < 64; kk++) {
            float4 a4 = *reinterpret_cast<const float4*>(&Qs[kk * 68 + ty * 4]);
            float4 b4 = *reinterpret_cast<const float4*>(&Ks[kk * 68 + tx * 4]);
            float a[4] = {a4.x, a4.y, a4.z, a4.w};
            float b[4] = {b4.x, b4.y, b4.z, b4.w};
#pragma unroll
            for (int i = 0; i < 4; i++)
#pragma unroll
                for (int j = 0; j < 4; j++) s[i][j] += a[i] * b[j];
        }

        // mask + exp + l accumulation + attn write
#pragma unroll
        for (int i = 0; i < 4; i++) {
            int4 mm = *reinterpret_cast<const int4*>(
                &mask[(q0 + ty * 4 + i) * T_ + kt + tx * 4]);
            if (mm.x == 0) s[i][0] = NEGV;
            if (mm.y == 0) s[i][1] = NEGV;
            if (mm.z == 0) s[i][2] = NEGV;
            if (mm.w == 0) s[i][3] = NEGV;
#pragma unroll
            for (int j = 0; j < 4; j++) {
                float e = __expf(s[i][j]);
                s[i][j] = e;
                lp[i] += e;
            }
            if (attn_out) {
                float4 o = make_float4(s[i][0], s[i][1], s[i][2], s[i][3]);
                *reinterpret_cast<float4*>(
                    &attn_out[((size_t)bh * T_ + q0 + ty * 4 + i) * T_ + kt + tx * 4]) = o;
            }
        }

        __syncthreads();  // score reads of Ks done; reuse as Pt[kc][q]
#pragma unroll
        for (int i = 0; i < 4; i++)
#pragma unroll
            for (int j = 0; j < 4; j++)
                Ks[(tx * 4 + j) * 68 + ty * 4 + i] = s[i][j];
        __syncthreads();

        // ctx += P @ V
#pragma unroll
        for (int kk = 0; kk < 64; kk++) {
            float4 a4 = *reinterpret_cast<const float4*>(&Ks[kk * 68 + ty * 4]);
            float4 b4 = *reinterpret_cast<const float4*>(&Vs[kk * 64 + tx * 4]);
            float a[4] = {a4.x, a4.y, a4.z, a4.w};
            float b[4] = {b4.x, b4.y, b4.z, b4.w};
#pragma unroll
            for (int i = 0; i < 4; i++)
#pragma unroll
                for (int j = 0; j < 4; j++) c[i][j] += a[i] * b[j];
        }
    }

    // reduce l across tx (16-lane groups), publish 1/l
#pragma unroll
    for (int i = 0; i < 4; i++) {
        float v = lp[i];
#pragma unroll
        for (int off = 8; off; off >>= 1)
            v += __shfl_xor_sync(0xffffffffu, v, off);
        if (tx == 0) sl[ty * 4 + i] = v;
    }
    __syncthreads();

#pragma unroll
    for (int i = 0; i < 4; i++) {
        float linv = 1.0f / sl[ty * 4 + i];
        int q = q0 + ty * 4 + i;
        if (tx == 0) g_linv[bh * T_ + q] = linv;
        float4 o = make_float4(c[i][0] * linv, c[i][1] * linv,
                               c[i][2] * linv, c[i][3] * linv);
        *reinterpret_cast<float4*>(&g_ctx[(bh * T_ + q) * D_ + tx * 4]) = o;
    }
}

// ---------------------------------------------------------------------------
// Kernel 2b: normalize attn rows by 1/l.
// ---------------------------------------------------------------------------
__global__ __launch_bounds__(256) void attn_norm_kernel(float4* __restrict__ attn) {
    int idx = blockIdx.x * 256 + threadIdx.x;
    int row = idx >> 8;
    float s = __ldg(&g_linv[row]);
    float4 v = attn[idx];
    v.x *= s; v.y *= s; v.z *= s; v.w *= s;
    attn[idx] = v;
}

// ---------------------------------------------------------------------------
// Kernel 3: out = gather(ctx) @ Wo^T + bo.  M=8192, N=64, K=1024.
// ---------------------------------------------------------------------------
__global__ __launch_bounds__(256) void outproj_kernel(
    const float* __restrict__ Wo, const float* __restrict__ bo,
    float* __restrict__ out) {
    __shared__ float As[64][65];
    __shared__ float Bs[64][65];
    const int m0 = blockIdx.x * 64;
    const int tid = threadIdx.x;
    const int tx = tid & 15, ty = tid >> 4;

    float acc[4][4];
#pragma unroll
    for (int i = 0; i < 4; i++)
#pragma unroll
        for (int j = 0; j < 4; j++) acc[i][j] = 0.0f;

    for (int h = 0; h < H_; h++) {
#pragma unroll
        for (int it = 0; it < 4; it++) {
            int lin = tid + it * 256;
            int r = lin >> 4;
            int d4 = (lin & 15) << 2;
            int m = m0 + r;
            int bb = m >> 10, t = m & 1023;
            float4 a = *reinterpret_cast<const float4*>(
                &g_ctx[((bb * H_ + h) * T_ + t) * D_ + d4]);
            As[r][d4 + 0] = a.x; As[r][d4 + 1] = a.y;
            As[r][d4 + 2] = a.z; As[r][d4 + 3] = a.w;
            float4 b = *reinterpret_cast<const float4*>(&Wo[r * DM_ + h * D_ + d4]);
            Bs[r][d4 + 0] = b.x; Bs[r][d4 + 1] = b.y;
            Bs[r][d4 + 2] = b.z; Bs[r][d4 + 3] = b.w;
        }
        __syncthreads();
#pragma unroll
        for (int kk = 0; kk < 64; kk++) {
            float a[4], b[4];
#pragma unroll
            for (int i = 0; i < 4; i++) a[i] = As[ty * 4 + i][kk];
#pragma unroll
            for (int j = 0; j < 4; j++) b[j] = Bs[tx * 4 + j][kk];
#pragma unroll
            for (int i = 0; i < 4; i++)
#pragma unroll
                for (int j = 0; j < 4; j++) acc[i][j] += a[i] * b[j];
        }
        __syncthreads();
    }
#pragma unroll
    for (int i = 0; i < 4; i++) {
        float4 o;
        o.x = acc[i][0] + bo[tx * 4 + 0];
        o.y = acc[i][1] + bo[tx * 4 + 1];
        o.z = acc[i][2] + bo[tx * 4 + 2];
        o.w = acc[i][3] + bo[tx * 4 + 3];
        *reinterpret_cast<float4*>(&out[(m0 + ty * 4 + i) * D_ + tx * 4]) = o;
    }
}

// ---------------------------------------------------------------------------

extern "C" void kernel_launch(void* const* d_in, const int* in_sizes, int n_in,
                              void* d_out, int out_size) {
    const float* q  = (const float*)d_in[0];
    const float* k  = (const float*)d_in[1];
    const float* v  = (const float*)d_in[2];
    const float* Wq = (const float*)d_in[3];
    const float* bq = (const float*)d_in[4];
    const float* Wk = (const float*)d_in[5];
    const float* bk = (const float*)d_in[6];
    const float* Wv = (const float*)d_in[7];
    const float* bv = (const float*)d_in[8];
    const float* Wo = (const float*)d_in[9];
    const float* bo = (const float*)d_in[10];
    const int* mask = (const int*)d_in[11];

    float* out = (float*)d_out;
    const long long OUTN  = (long long)B_ * T_ * D_;          // 524288
    const long long ATTNN = (long long)BH_ * T_ * T_;         // 134217728
    float* attn = ((long long)out_size >= OUTN + ATTNN) ? (out + OUTN) : nullptr;

    float *qh, *kh, *vh;
    cudaGetSymbolAddress((void**)&qh, g_qh);
    cudaGetSymbolAddress((void**)&kh, g_kh);
    cudaGetSymbolAddress((void**)&vh, g_vh);

    cudaFuncSetAttribute(attn_kernel,
                         cudaFuncAttributeMaxDynamicSharedMemorySize, ATTN_SMEM);

    dim3 gp(DM_ / 128, (B_ * T_) / 128);   // (8, 64)
    proj_mma_kernel<<<gp, 256, PROJ_SMEM>>>(q, Wq, bq, qh);
    proj_mma_kernel<<<gp, 256, PROJ_SMEM>>>(k, Wk, bk, kh);
    proj_mma_kernel<<<gp, 256, PROJ_SMEM>>>(v, Wv, bv, vh);

    attn_kernel<<<dim3(T_ / 64, BH_), 256, ATTN_SMEM>>>(mask, attn);

    if (attn) {
        attn_norm_kernel<<<(int)(ATTNN / 4 / 256), 256>>>(
            reinterpret_cast<float4*>(attn));
    }

    outproj_kernel<<<(B_ * T_) / 64, 256>>>(Wo, bo, out);
}

// round 11
// speedup vs baseline: 1.0006x; 1.0006x over previous
#include <cuda_runtime.h>
#include <cuda_bf16.h>
#include <cstdint>

#define B_  8
#define T_  1024
#define DM_ 1024
#define H_  16
#define D_  64
#define BH_ (B_ * H_)
#define NEGV (-1.0e9f)

// Scratch (allocation-free rule: __device__ globals)
__device__ float g_qh[BH_ * T_ * D_];
__device__ float g_kh[BH_ * T_ * D_];
__device__ float g_vh[BH_ * T_ * D_];
__device__ float g_ctx[BH_ * T_ * D_];
__device__ float g_linv[BH_ * T_];

// ---------------------------------------------------------------------------
// mma.sync bf16 (baseline PTX -> legacy HMMA on sm_103)
// ---------------------------------------------------------------------------
__device__ __forceinline__ void mma_bf16(float c[4],
                                         uint32_t a0, uint32_t a1,
                                         uint32_t a2, uint32_t a3,
                                         uint32_t b0, uint32_t b1) {
    asm volatile(
        "mma.sync.aligned.m16n8k16.row.col.f32.bf16.bf16.f32 "
        "{%0,%1,%2,%3}, {%4,%5,%6,%7}, {%8,%9}, {%0,%1,%2,%3};"
        : "+f"(c[0]), "+f"(c[1]), "+f"(c[2]), "+f"(c[3])
        : "r"(a0), "r"(a1), "r"(a2), "r"(a3), "r"(b0), "r"(b1));
}

__device__ __forceinline__ uint32_t pack_bf16x2(float x, float y) {
    __nv_bfloat162 h = __floats2bfloat162_rn(x, y);
    return *reinterpret_cast<uint32_t*>(&h);
}

// ---------------------------------------------------------------------------
// Kernel 1: projection GEMM via mma.sync bf16x3 (hi/lo split).
// C[m][n] = sum_k X[m][k]*W[n][k] + bias[n];  M=8192, N=1024, K=1024.
// CTA 128x128, 8 warps (2x4), warp tile 64x32, K-chunk 32.
// ---------------------------------------------------------------------------
#define KC 32
#define PITCH 20
#define TILE_U32 (128 * PITCH)
#define PROJ_SMEM (4 * TILE_U32 * 4)

__global__ __launch_bounds__(256) void proj_mma_kernel(
    const float* __restrict__ X, const float* __restrict__ W,
    const float* __restrict__ bias, float* __restrict__ out) {
    extern __shared__ uint32_t sm[];
    uint32_t* Ahi = sm;
    uint32_t* Alo = sm + TILE_U32;
    uint32_t* Bhi = sm + 2 * TILE_U32;
    uint32_t* Blo = sm + 3 * TILE_U32;

    const int tid = threadIdx.x;
    const int lane = tid & 31;
    const int warp = tid >> 5;
    const int wm = (warp >> 2) * 64;
    const int wn = (warp & 3) * 32;

    const int m0 = blockIdx.y * 128;
    const int n0 = blockIdx.x * 128;

    float c[4][4][4];
#pragma unroll
    for (int mi = 0; mi < 4; mi++)
#pragma unroll
        for (int nj = 0; nj < 4; nj++)
#pragma unroll
            for (int r = 0; r < 4; r++) c[mi][nj][r] = 0.0f;

    const int fr[4] = {(tid) >> 3, (tid + 256) >> 3, (tid + 512) >> 3, (tid + 768) >> 3};
    const int fc = (tid & 7) * 4;
    const int fc2 = (tid & 7) * 2;

    float4 ax[4], bx[4];
#pragma unroll
    for (int q = 0; q < 4; q++) {
        ax[q] = *reinterpret_cast<const float4*>(&X[(m0 + fr[q]) * DM_ + fc]);
        bx[q] = *reinterpret_cast<const float4*>(&W[(n0 + fr[q]) * DM_ + fc]);
    }

    for (int i = 0; i < DM_ / KC; i++) {
#pragma unroll
        for (int q = 0; q < 4; q++) {
            float4 v = ax[q];
            float hx = __bfloat162float(__float2bfloat16_rn(v.x));
            float hy = __bfloat162float(__float2bfloat16_rn(v.y));
            float hz = __bfloat162float(__float2bfloat16_rn(v.z));
            float hw = __bfloat162float(__float2bfloat16_rn(v.w));
            int base = fr[q] * PITCH + fc2;
            Ahi[base + 0] = pack_bf16x2(hx, hy);
            Ahi[base + 1] = pack_bf16x2(hz, hw);
            Alo[base + 0] = pack_bf16x2(v.x - hx, v.y - hy);
            Alo[base + 1] = pack_bf16x2(v.z - hz, v.w - hw);

            v = bx[q];
            hx = __bfloat162float(__float2bfloat16_rn(v.x));
            hy = __bfloat162float(__float2bfloat16_rn(v.y));
            hz = __bfloat162float(__float2bfloat16_rn(v.z));
            hw = __bfloat162float(__float2bfloat16_rn(v.w));
            Bhi[base + 0] = pack_bf16x2(hx, hy);
            Bhi[base + 1] = pack_bf16x2(hz, hw);
            Blo[base + 0] = pack_bf16x2(v.x - hx, v.y - hy);
            Blo[base + 1] = pack_bf16x2(v.z - hz, v.w - hw);
        }
        __syncthreads();

        if (i + 1 < DM_ / KC) {
            const int k0 = (i + 1) * KC;
#pragma unroll
            for (int q = 0; q < 4; q++) {
                ax[q] = *reinterpret_cast<const float4*>(&X[(m0 + fr[q]) * DM_ + k0 + fc]);
                bx[q] = *reinterpret_cast<const float4*>(&W[(n0 + fr[q]) * DM_ + k0 + fc]);
            }
        }

#pragma unroll
        for (int kb = 0; kb < 2; kb++) {
            const int cc = kb * 8 + (lane & 3);
            uint32_t ah[4][4], al[4][4], bh[4][2], bl[4][2];
#pragma unroll
            for (int mi = 0; mi < 4; mi++) {
                int r0 = wm + mi * 16 + (lane >> 2);
                ah[mi][0] = Ahi[r0 * PITCH + cc];
                ah[mi][1] = Ahi[(r0 + 8) * PITCH + cc];
                ah[mi][2] = Ahi[r0 * PITCH + cc + 4];
                ah[mi][3] = Ahi[(r0 + 8) * PITCH + cc + 4];
                al[mi][0] = Alo[r0 * PITCH + cc];
                al[mi][1] = Alo[(r0 + 8) * PITCH + cc];
                al[mi][2] = Alo[r0 * PITCH + cc + 4];
                al[mi][3] = Alo[(r0 + 8) * PITCH + cc + 4];
            }
#pragma unroll
            for (int nj = 0; nj < 4; nj++) {
                int nr = wn + nj * 8 + (lane >> 2);
                bh[nj][0] = Bhi[nr * PITCH + cc];
                bh[nj][1] = Bhi[nr * PITCH + cc + 4];
                bl[nj][0] = Blo[nr * PITCH + cc];
                bl[nj][1] = Blo[nr * PITCH + cc + 4];
            }
#pragma unroll
            for (int mi = 0; mi < 4; mi++)
#pragma unroll
                for (int nj = 0; nj < 4; nj++) {
                    mma_bf16(c[mi][nj], ah[mi][0], ah[mi][1], ah[mi][2], ah[mi][3],
                             bh[nj][0], bh[nj][1]);
                    mma_bf16(c[mi][nj], ah[mi][0], ah[mi][1], ah[mi][2], ah[mi][3],
                             bl[nj][0], bl[nj][1]);
                    mma_bf16(c[mi][nj], al[mi][0], al[mi][1], al[mi][2], al[mi][3],
                             bh[nj][0], bh[nj][1]);
                }
        }
        __syncthreads();
    }

#pragma unroll
    for (int mi = 0; mi < 4; mi++) {
        int r0 = m0 + wm + mi * 16 + (lane >> 2);
#pragma unroll
        for (int nj = 0; nj < 4; nj++) {
            int n = n0 + wn + nj * 8 + (lane & 3) * 2;
            int h = n >> 6, dd = n & 63;
            float b0 = bias[n], b1 = bias[n + 1];
#pragma unroll
            for (int half = 0; half < 2; half++) {
                int r = r0 + half * 8;
                int bb = r >> 10, t = r & 1023;
                float2 o;
                o.x = c[mi][nj][half * 2 + 0] + b0;
                o.y = c[mi][nj][half * 2 + 1] + b1;
                *reinterpret_cast<float2*>(
                    &out[(((size_t)bb * H_ + h) * T_ + t) * D_ + dd]) = o;
            }
        }
    }
}

// ---------------------------------------------------------------------------
// Kernel 2: single-pass attention, R1-proven 64x64 tiling.
// Per 64-col k-tile: s = (Q/8)K^T, mask, e = exp(s) (no max subtraction:
// scores are O(1)), write e unnormalized to attn_out, lp += e,
// ctx += e @ V via Pt staging (pitch 68, q<64: valid).
// ---------------------------------------------------------------------------
#define ATTN_SMEM ((4352 + 4352 + 4096 + 64) * 4)

__global__ __launch_bounds__(256) void attn_kernel(
    const int* __restrict__ mask, float* __restrict__ attn_out) {
    extern __shared__ float sh[];
    float* Qs = sh;             // [64 d][68 q]
    float* Ks = sh + 4352;      // [64 d][68 k]; reused as Pt[64 kc][68 q]
    float* Vs = sh + 8704;      // [64 k][64 d]
    float* sl = sh + 12800;     // [64]

    const int bh = blockIdx.y;
    const int q0 = blockIdx.x * 64;
    const int tid = threadIdx.x;
    const int tx = tid & 15, ty = tid >> 4;

    // Load Q tile (64 x 64) transposed + prescaled by 1/sqrt(D)
#pragma unroll
    for (int it = 0; it < 4; it++) {
        int f = tid + it * 256;
        int r = f >> 4;
        int d4 = (f & 15) << 2;
        float4 v = *reinterpret_cast<const float4*>(&g_qh[(bh * T_ + q0 + r) * D_ + d4]);
        Qs[(d4 + 0) * 68 + r] = v.x * 0.125f;
        Qs[(d4 + 1) * 68 + r] = v.y * 0.125f;
        Qs[(d4 + 2) * 68 + r] = v.z * 0.125f;
        Qs[(d4 + 3) * 68 + r] = v.w * 0.125f;
    }

    float c[4][4];
    float lp[4];
#pragma unroll
    for (int i = 0; i < 4; i++) {
        lp[i] = 0.0f;
#pragma unroll
        for (int j = 0; j < 4; j++) c[i][j] = 0.0f;
    }

    for (int kt = 0; kt < T_; kt += 64) {
        __syncthreads();  // prior Pt/Vs reads done (also covers Qs fill)
#pragma unroll
        for (int it = 0; it < 4; it++) {
            int f = tid + it * 256;
            int r = f >> 4;
            int d4 = (f & 15) << 2;
            float4 kv = *reinterpret_cast<const float4*>(&g_kh[(bh * T_ + kt + r) * D_ + d4]);
            Ks[(d4 + 0) * 68 + r] = kv.x;
            Ks[(d4 + 1) * 68 + r] = kv.y;
            Ks[(d4 + 2) * 68 + r] = kv.z;
            Ks[(d4 + 3) * 68 + r] = kv.w;
            float4 vv = *reinterpret_cast<const float4*>(&g_vh[(bh * T_ + kt + r) * D_ + d4]);
            *reinterpret_cast<float4*>(&Vs[r * 64 + d4]) = vv;
        }
        __syncthreads();

        // scores: rows q0+ty*4+i, cols kt+tx*4+j
        float s[4][4];
#pragma unroll
        for (int i = 0; i < 4; i++)
#pragma unroll
            for (int j = 0; j < 4; j++) s[i][j] = 0.0f;
#pragma unroll
        for (int kk = 0; kk < 64; kk++) {
            float4 a4 = *reinterpret_cast<const float4*>(&Qs[kk * 68 + ty * 4]);
            float4 b4 = *reinterpret_cast<const float4*>(&Ks[kk * 68 + tx * 4]);
            float a[4] = {a4.x, a4.y, a4.z, a4.w};
            float b[4] = {b4.x, b4.y, b4.z, b4.w};
#pragma unroll
            for (int i = 0; i < 4; i++)
#pragma unroll
                for (int j = 0; j < 4; j++) s[i][j] += a[i] * b[j];
        }

        // mask + exp + l accumulation + attn write
#pragma unroll
        for (int i = 0; i < 4; i++) {
            int4 mm = *reinterpret_cast<const int4*>(
                &mask[(q0 + ty * 4 + i) * T_ + kt + tx * 4]);
            if (mm.x == 0) s[i][0] = NEGV;
            if (mm.y == 0) s[i][1] = NEGV;
            if (mm.z == 0) s[i][2] = NEGV;
            if (mm.w == 0) s[i][3] = NEGV;
#pragma unroll
            for (int j = 0; j < 4; j++) {
                float e = __expf(s[i][j]);
                s[i][j] = e;
                lp[i] += e;
            }
            if (attn_out) {
                float4 o = make_float4(s[i][0], s[i][1], s[i][2], s[i][3]);
                *reinterpret_cast<float4*>(
                    &attn_out[((size_t)bh * T_ + q0 + ty * 4 + i) * T_ + kt + tx * 4]) = o;
            }
        }

        __syncthreads();  // score reads of Ks done; reuse as Pt[kc][q]
#pragma unroll
        for (int i = 0; i < 4; i++)
#pragma unroll
            for (int j = 0; j < 4; j++)
                Ks[(tx * 4 + j) * 68 + ty * 4 + i] = s[i][j];
        __syncthreads();

        // ctx += P @ V
#pragma unroll
        for (int kk = 0; kk < 64; kk++) {
            float4 a4 = *reinterpret_cast<const float4*>(&Ks[kk * 68 + ty * 4]);
            float4 b4 = *reinterpret_cast<const float4*>(&Vs[kk * 64 + tx * 4]);
            float a[4] = {a4.x, a4.y, a4.z, a4.w};
            float b[4] = {b4.x, b4.y, b4.z, b4.w};
#pragma unroll
            for (int i = 0; i < 4; i++)
#pragma unroll
                for (int j = 0; j < 4; j++) c[i][j] += a[i] * b[j];
        }
    }

    // reduce l across tx (16-lane groups), publish 1/l
#pragma unroll
    for (int i = 0; i < 4; i++) {
        float v = lp[i];
#pragma unroll
        for (int off = 8; off; off >>= 1)
            v += __shfl_xor_sync(0xffffffffu, v, off);
        if (tx == 0) sl[ty * 4 + i] = v;
    }
    __syncthreads();

#pragma unroll
    for (int i = 0; i < 4; i++) {
        float linv = 1.0f / sl[ty * 4 + i];
        int q = q0 + ty * 4 + i;
        if (tx == 0) g_linv[bh * T_ + q] = linv;
        float4 o = make_float4(c[i][0] * linv, c[i][1] * linv,
                               c[i][2] * linv, c[i][3] * linv);
        *reinterpret_cast<float4*>(&g_ctx[(bh * T_ + q) * D_ + tx * 4]) = o;
    }
}

// ---------------------------------------------------------------------------
// Kernel 2b: normalize attn rows by 1/l.
// ---------------------------------------------------------------------------
__global__ __launch_bounds__(256) void attn_norm_kernel(float4* __restrict__ attn) {
    int idx = blockIdx.x * 256 + threadIdx.x;
    int row = idx >> 8;
    float s = __ldg(&g_linv[row]);
    float4 v = attn[idx];
    v.x *= s; v.y *= s; v.z *= s; v.w *= s;
    attn[idx] = v;
}

// ---------------------------------------------------------------------------
// Kernel 3: out = gather(ctx) @ Wo^T + bo.  M=8192, N=64, K=1024.
// ---------------------------------------------------------------------------
__global__ __launch_bounds__(256) void outproj_kernel(
    const float* __restrict__ Wo, const float* __restrict__ bo,
    float* __restrict__ out) {
    __shared__ float As[64][65];
    __shared__ float Bs[64][65];
    const int m0 = blockIdx.x * 64;
    const int tid = threadIdx.x;
    const int tx = tid & 15, ty = tid >> 4;

    float acc[4][4];
#pragma unroll
    for (int i = 0; i < 4; i++)
#pragma unroll
        for (int j = 0; j < 4; j++) acc[i][j] = 0.0f;

    for (int h = 0; h < H_; h++) {
#pragma unroll
        for (int it = 0; it < 4; it++) {
            int lin = tid + it * 256;
            int r = lin >> 4;
            int d4 = (lin & 15) << 2;
            int m = m0 + r;
            int bb = m >> 10, t = m & 1023;
            float4 a = *reinterpret_cast<const float4*>(
                &g_ctx[((bb * H_ + h) * T_ + t) * D_ + d4]);
            As[r][d4 + 0] = a.x; As[r][d4 + 1] = a.y;
            As[r][d4 + 2] = a.z; As[r][d4 + 3] = a.w;
            float4 b = *reinterpret_cast<const float4*>(&Wo[r * DM_ + h * D_ + d4]);
            Bs[r][d4 + 0] = b.x; Bs[r][d4 + 1] = b.y;
            Bs[r][d4 + 2] = b.z; Bs[r][d4 + 3] = b.w;
        }
        __syncthreads();
#pragma unroll
        for (int kk = 0; kk < 64; kk++) {
            float a[4], b[4];
#pragma unroll
            for (int i = 0; i < 4; i++) a[i] = As[ty * 4 + i][kk];
#pragma unroll
            for (int j = 0; j < 4; j++) b[j] = Bs[tx * 4 + j][kk];
#pragma unroll
            for (int i = 0; i < 4; i++)
#pragma unroll
                for (int j = 0; j < 4; j++) acc[i][j] += a[i] * b[j];
        }
        __syncthreads();
    }
#pragma unroll
    for (int i = 0; i < 4; i++) {
        float4 o;
        o.x = acc[i][0] + bo[tx * 4 + 0];
        o.y = acc[i][1] + bo[tx * 4 + 1];
        o.z = acc[i][2] + bo[tx * 4 + 2];
        o.w = acc[i][3] + bo[tx * 4 + 3];
        *reinterpret_cast<float4*>(&out[(m0 + ty * 4 + i) * D_ + tx * 4]) = o;
    }
}

// ---------------------------------------------------------------------------

extern "C" void kernel_launch(void* const* d_in, const int* in_sizes, int n_in,
                              void* d_out, int out_size) {
    const float* q  = (const float*)d_in[0];
    const float* k  = (const float*)d_in[1];
    const float* v  = (const float*)d_in[2];
    const float* Wq = (const float*)d_in[3];
    const float* bq = (const float*)d_in[4];
    const float* Wk = (const float*)d_in[5];
    const float* bk = (const float*)d_in[6];
    const float* Wv = (const float*)d_in[7];
    const float* bv = (const float*)d_in[8];
    const float* Wo = (const float*)d_in[9];
    const float* bo = (const float*)d_in[10];
    const int* mask = (const int*)d_in[11];

    float* out = (float*)d_out;
    const long long OUTN  = (long long)B_ * T_ * D_;          // 524288
    const long long ATTNN = (long long)BH_ * T_ * T_;         // 134217728
    float* attn = ((long long)out_size >= OUTN + ATTNN) ? (out + OUTN) : nullptr;

    float *qh, *kh, *vh;
    cudaGetSymbolAddress((void**)&qh, g_qh);
    cudaGetSymbolAddress((void**)&kh, g_kh);
    cudaGetSymbolAddress((void**)&vh, g_vh);

    cudaFuncSetAttribute(attn_kernel,
                         cudaFuncAttributeMaxDynamicSharedMemorySize, ATTN_SMEM);

    dim3 gp(DM_ / 128, (B_ * T_) / 128);   // (8, 64)
    proj_mma_kernel<<<gp, 256, PROJ_SMEM>>>(q, Wq, bq, qh);
    proj_mma_kernel<<<gp, 256, PROJ_SMEM>>>(k, Wk, bk, kh);
    proj_mma_kernel<<<gp, 256, PROJ_SMEM>>>(v, Wv, bv, vh);

    attn_kernel<<<dim3(T_ / 64, BH_), 256, ATTN_SMEM>>>(mask, attn);

    if (attn) {
        attn_norm_kernel<<<(int)(ATTNN / 4 / 256), 256>>>(
            reinterpret_cast<float4*>(attn));
    }

    outproj_kernel<<<(B_ * T_) / 64, 256>>>(Wo, bo, out);
}